// round 10
// baseline (speedup 1.0000x reference)
#include <cuda_runtime.h>
#include <cuda_bf16.h>
#include <cstdint>

// Problem constants
#define BATCH 4096
#define TT    120
#define II    64
#define HH    128
#define G3    384   // 3*H

// 755MB fp32 scratch for precomputed input gates, layout [T][B][3H]
__device__ float g_xg[(size_t)TT * BATCH * G3];

__device__ __forceinline__ float sigf(float v) {
    return __fdividef(1.0f, 1.0f + __expf(-v));
}
__device__ __forceinline__ float tanhf_fast(float v) {
    return __fdividef(2.0f, 1.0f + __expf(-2.0f * v)) - 1.0f;
}

// ---------------- tensor-core helpers ----------------
__device__ __forceinline__ uint32_t s2u(const void* p) {
    return (uint32_t)__cvta_generic_to_shared(p);
}
__device__ __forceinline__ void ldsm_x4(uint32_t a[4], uint32_t addr) {
    asm volatile("ldmatrix.sync.aligned.m8n8.x4.shared.b16 {%0,%1,%2,%3}, [%4];"
                 : "=r"(a[0]), "=r"(a[1]), "=r"(a[2]), "=r"(a[3]) : "r"(addr));
}
// B operand: W stored [n][k] row-major == col-major B(k x n): load WITHOUT trans
__device__ __forceinline__ void ldsm_x2(uint32_t b[2], uint32_t addr) {
    asm volatile("ldmatrix.sync.aligned.m8n8.x2.shared.b16 {%0,%1}, [%2];"
                 : "=r"(b[0]), "=r"(b[1]) : "r"(addr));
}
__device__ __forceinline__ void mma16816(float c[4], const uint32_t a[4],
                                         const uint32_t b[2]) {
    asm volatile(
        "mma.sync.aligned.m16n8k16.row.col.f32.bf16.bf16.f32 "
        "{%0,%1,%2,%3}, {%4,%5,%6,%7}, {%8,%9}, {%0,%1,%2,%3};"
        : "+f"(c[0]), "+f"(c[1]), "+f"(c[2]), "+f"(c[3])
        : "r"(a[0]), "r"(a[1]), "r"(a[2]), "r"(a[3]), "r"(b[0]), "r"(b[1]));
}
// pack (lo_elem, hi_elem) floats -> bf16x2 with rounding (lo_elem in low half)
__device__ __forceinline__ uint32_t cvt_bf16x2(float lo_elem, float hi_elem) {
    uint32_t d;
    asm("cvt.rn.bf16x2.f32 %0, %1, %2;" : "=r"(d) : "f"(hi_elem), "f"(lo_elem));
    return d;
}
// pack two already-converted bf16 (a -> low half)
__device__ __forceinline__ uint32_t pack_bf16x2(__nv_bfloat16 a, __nv_bfloat16 b) {
    uint32_t d;
    asm("mov.b32 %0, {%1, %2};" : "=r"(d)
        : "h"(*(const unsigned short*)&a), "h"(*(const unsigned short*)&b));
    return d;
}

// =====================================================================
// Kernel 1: x_gates via tensor cores (bf16 hi/lo 3-pass mma).
// (unchanged from R9 — ~262us, near DRAM floor)
// =====================================================================
#define XW   72                  // padded k-row length (144B stride)
#define NT2  (TT * (BATCH / 64)) // 7680 tiles
#define XP2_SMEM_BYTES ((G3 * XW * 2 + 64 * XW * 2) * 2)   // 129024

__global__ void __launch_bounds__(512, 1)
xproj_mma_kernel(const float* __restrict__ x,
                 const float* __restrict__ Wih,
                 const float* __restrict__ bih)
{
    extern __shared__ __align__(16) char smemc[];
    __nv_bfloat16* Whi = reinterpret_cast<__nv_bfloat16*>(smemc);
    __nv_bfloat16* Wlo = Whi + G3 * XW;
    __nv_bfloat16* Xhi = Wlo + G3 * XW;
    __nv_bfloat16* Xlo = Xhi + 64 * XW;

    const int tid   = threadIdx.x;
    const int w     = tid >> 5;
    const int lane  = tid & 31;
    const int g8    = lane >> 2;
    const int cc    = lane & 3;
    const int jbase = w * 8;
    const int j0    = jbase + 2 * cc;

    for (int i = tid; i < G3 * II; i += 512) {
        int n = i >> 6, k = i & 63;
        float v = Wih[i];
        __nv_bfloat16 hi = __float2bfloat16(v);
        Whi[n * XW + k] = hi;
        Wlo[n * XW + k] = __float2bfloat16(v - __bfloat162float(hi));
    }

    const float bR0 = bih[j0],       bR1 = bih[j0 + 1];
    const float bZ0 = bih[128 + j0], bZ1 = bih[128 + j0 + 1];
    const float bN0 = bih[256 + j0], bN1 = bih[256 + j0 + 1];

    const int arow = lane & 15;
    const int acol = (lane >> 4) * 8;
    uint32_t aHi[4], aLo[4];
#pragma unroll
    for (int mt = 0; mt < 4; ++mt) {
        aHi[mt] = s2u(Xhi + (mt * 16 + arow) * XW + acol);
        aLo[mt] = s2u(Xlo + (mt * 16 + arow) * XW + acol);
    }
    const int l16  = lane & 15;
    const int brow = l16 & 7;
    const int bkh  = (l16 >> 3) & 1;
    uint32_t bHi[3], bLo[3];
#pragma unroll
    for (int g = 0; g < 3; ++g) {
        int nb = g * 128 + jbase;
        bHi[g] = s2u(Whi + (nb + brow) * XW + 8 * bkh);
        bLo[g] = s2u(Wlo + (nb + brow) * XW + 8 * bkh);
    }

    const int xrow = tid >> 3;
    const int xcol = (tid & 7) * 8;
    float4 pa, pb;

    int tile = blockIdx.x;
    if (tile < NT2) {
        int t = tile % TT, b0 = (tile / TT) << 6;
        const float4* p = reinterpret_cast<const float4*>(
            x + ((size_t)(b0 + xrow) * TT + t) * II + xcol);
        pa = p[0]; pb = p[1];
    }

    for (; tile < NT2; tile += 148) {
        const int t  = tile % TT;
        const int b0 = (tile / TT) << 6;

        __syncthreads();

        {
            float v[8] = {pa.x, pa.y, pa.z, pa.w, pb.x, pb.y, pb.z, pb.w};
            __nv_bfloat16* hp = Xhi + xrow * XW + xcol;
            __nv_bfloat16* lp = Xlo + xrow * XW + xcol;
#pragma unroll
            for (int e = 0; e < 4; ++e) {
                float a0 = v[2 * e], a1 = v[2 * e + 1];
                __nv_bfloat16 h0 = __float2bfloat16(a0);
                __nv_bfloat16 h1 = __float2bfloat16(a1);
                *reinterpret_cast<uint32_t*>(hp + 2 * e) = pack_bf16x2(h0, h1);
                *reinterpret_cast<uint32_t*>(lp + 2 * e) =
                    cvt_bf16x2(a0 - __bfloat162float(h0), a1 - __bfloat162float(h1));
            }
        }

        {
            int nxt = tile + 148;
            if (nxt < NT2) {
                int tn = nxt % TT, bn = (nxt / TT) << 6;
                const float4* p = reinterpret_cast<const float4*>(
                    x + ((size_t)(bn + xrow) * TT + tn) * II + xcol);
                pa = p[0]; pb = p[1];
            }
        }

        __syncthreads();

        float C[4][3][4];
#pragma unroll
        for (int mt = 0; mt < 4; ++mt)
#pragma unroll
            for (int g = 0; g < 3; ++g)
#pragma unroll
                for (int e = 0; e < 4; ++e) C[mt][g][e] = 0.0f;

#pragma unroll
        for (int c8 = 0; c8 < 4; ++c8) {
            const uint32_t off = c8 * 32;
            uint32_t ahi[4][4], alo[4][4];
#pragma unroll
            for (int mt = 0; mt < 4; ++mt) {
                ldsm_x4(ahi[mt], aHi[mt] + off);
                ldsm_x4(alo[mt], aLo[mt] + off);
            }
#pragma unroll
            for (int g = 0; g < 3; ++g) {
                uint32_t bh[2], bl_[2];
                ldsm_x2(bh,  bHi[g] + off);
                ldsm_x2(bl_, bLo[g] + off);
#pragma unroll
                for (int mt = 0; mt < 4; ++mt) {
                    mma16816(C[mt][g], ahi[mt], bh);
                    mma16816(C[mt][g], alo[mt], bh);
                    mma16816(C[mt][g], ahi[mt], bl_);
                }
            }
        }

#pragma unroll
        for (int mt = 0; mt < 4; ++mt) {
#pragma unroll
            for (int rp = 0; rp < 2; ++rp) {
                int row = mt * 16 + g8 + rp * 8;
                float* dst = g_xg + ((size_t)t * BATCH + b0 + row) * G3 + j0;
                float2 o;
                o.x = C[mt][0][rp * 2] + bR0; o.y = C[mt][0][rp * 2 + 1] + bR1;
                *reinterpret_cast<float2*>(dst) = o;
                o.x = C[mt][1][rp * 2] + bZ0; o.y = C[mt][1][rp * 2 + 1] + bZ1;
                *reinterpret_cast<float2*>(dst + 128) = o;
                o.x = C[mt][2][rp * 2] + bN0; o.y = C[mt][2][rp * 2 + 1] + bN1;
                *reinterpret_cast<float2*>(dst + 256) = o;
            }
        }
    }
}

// =====================================================================
// Kernel 2: GRU recurrence, 1024 threads (32 warps = 8/SMSP).
// Warp w: m-tile mt = w>>4 (16 rows), n-cols jbase = (w&15)*8 for all
// 3 gates. B frags for gates 0+1 fetched with ONE ldsm_x4 (lane groups
// 16-31 target gate 1's rows); gate 2 via ldsm_x2.
// SMEM: Whi/Wlo [384][136] bf16, Hhi/Hlo [32][136] bf16. 226.3 KB.
// =====================================================================
#define WPAD  136
#define R_SMEM_BYTES ((384 * WPAD * 2 + 32 * WPAD * 2) * 2)   // 226304

__global__ void __launch_bounds__(1024, 1)
gru_mma_kernel(const float* __restrict__ Whh,
               const float* __restrict__ bhh,
               float* __restrict__ out,
               int write_hT)
{
    extern __shared__ __align__(16) char smemc[];
    __nv_bfloat16* Whi = reinterpret_cast<__nv_bfloat16*>(smemc);
    __nv_bfloat16* Wlo = Whi + 384 * WPAD;
    __nv_bfloat16* Hhi = Wlo + 384 * WPAD;
    __nv_bfloat16* Hlo = Hhi + 32 * WPAD;

    const int tid   = threadIdx.x;
    const int w     = tid >> 5;          // 0..31
    const int lane  = tid & 31;
    const int mt    = w >> 4;            // 0..1  (m-tile: 16 rows)
    const int jbase = (w & 15) * 8;
    const int g8    = lane >> 2;
    const int cc    = lane & 3;
    const int j0    = jbase + 2 * cc;
    const int b0    = blockIdx.x * 32;

    for (int i = tid; i < G3 * HH; i += 1024) {
        int n = i >> 7, k = i & 127;
        float v = Whh[i];
        __nv_bfloat16 hi = __float2bfloat16(v);
        Whi[n * WPAD + k] = hi;
        Wlo[n * WPAD + k] = __float2bfloat16(v - __bfloat162float(hi));
    }
    for (int i = tid; i < 32 * WPAD; i += 1024) {
        Hhi[i] = __float2bfloat16(0.0f);
        Hlo[i] = __float2bfloat16(0.0f);
    }

    const float bR0 = bhh[j0],       bR1 = bhh[j0 + 1];
    const float bZ0 = bhh[128 + j0], bZ1 = bhh[128 + j0 + 1];
    const float bN0 = bhh[256 + j0], bN1 = bhh[256 + j0 + 1];

    __syncthreads();

    // A (h): x4 over this warp's 16 rows
    const int arow = lane & 15;
    const int acol = (lane >> 4) * 8;
    const uint32_t aHi = s2u(Hhi + (mt * 16 + arow) * WPAD + acol);
    const uint32_t aLo = s2u(Hlo + (mt * 16 + arow) * WPAD + acol);

    // B gates 0+1 merged x4: lane>>4 selects gate, (lane&15) as x2 pattern
    const int bg   = lane >> 4;          // 0 or 1 (gate select)
    const int l16  = lane & 15;
    const int brow = l16 & 7;
    const int bkh  = (l16 >> 3) & 1;
    const uint32_t b01Hi = s2u(Whi + (bg * 128 + jbase + brow) * WPAD + 8 * bkh);
    const uint32_t b01Lo = s2u(Wlo + (bg * 128 + jbase + brow) * WPAD + 8 * bkh);
    // B gate 2 x2
    const uint32_t b2Hi = s2u(Whi + (256 + jbase + brow) * WPAD + 8 * bkh);
    const uint32_t b2Lo = s2u(Wlo + (256 + jbase + brow) * WPAD + 8 * bkh);

    float hold[2][2];
#pragma unroll
    for (int q = 0; q < 2; ++q) { hold[q][0] = 0.0f; hold[q][1] = 0.0f; }

    for (int t = 0; t < TT; ++t) {
        float C[3][4];
#pragma unroll
        for (int g = 0; g < 3; ++g)
#pragma unroll
            for (int e = 0; e < 4; ++e) C[g][e] = 0.0f;

#pragma unroll
        for (int c8 = 0; c8 < 8; ++c8) {
            const uint32_t off = c8 * 32;
            uint32_t ah[4], al[4];
            ldsm_x4(ah, aHi + off);
            ldsm_x4(al, aLo + off);
            uint32_t b01h[4], b01l[4], b2h[2], b2l[2];
            ldsm_x4(b01h, b01Hi + off);
            ldsm_x4(b01l, b01Lo + off);
            ldsm_x2(b2h, b2Hi + off);
            ldsm_x2(b2l, b2Lo + off);
            // gate 0: b01*[0..1], gate 1: b01*[2..3], gate 2: b2*
            mma16816(C[0], ah, b01h + 0);
            mma16816(C[0], al, b01h + 0);
            mma16816(C[0], ah, b01l + 0);
            mma16816(C[1], ah, b01h + 2);
            mma16816(C[1], al, b01h + 2);
            mma16816(C[1], ah, b01l + 2);
            mma16816(C[2], ah, b2h);
            mma16816(C[2], al, b2h);
            mma16816(C[2], ah, b2l);
        }

        // input gates (after mma loop to keep in-loop reg pressure low;
        // DRAM latency overlapped by other warps' mma work)
        float2 xr[2], xz[2], xn[2];
#pragma unroll
        for (int rp = 0; rp < 2; ++rp) {
            int row = mt * 16 + g8 + rp * 8;
            const float* rowp = g_xg + ((size_t)t * BATCH + b0 + row) * G3 + j0;
            xr[rp] = *reinterpret_cast<const float2*>(rowp);
            xz[rp] = *reinterpret_cast<const float2*>(rowp + 128);
            xn[rp] = *reinterpret_cast<const float2*>(rowp + 256);
        }

        __syncthreads();   // all ldmatrix reads of h done before rewrite

#pragma unroll
        for (int rp = 0; rp < 2; ++rp) {
            const int row = mt * 16 + g8 + rp * 8;
            float hr0 = C[0][rp * 2], hr1 = C[0][rp * 2 + 1];
            float hz0 = C[1][rp * 2], hz1 = C[1][rp * 2 + 1];
            float hn0 = C[2][rp * 2], hn1 = C[2][rp * 2 + 1];

            float r0 = sigf(xr[rp].x + hr0 + bR0);
            float r1 = sigf(xr[rp].y + hr1 + bR1);
            float z0 = sigf(xz[rp].x + hz0 + bZ0);
            float z1 = sigf(xz[rp].y + hz1 + bZ1);
            float n0 = tanhf_fast(xn[rp].x + r0 * (hn0 + bN0));
            float n1 = tanhf_fast(xn[rp].y + r1 * (hn1 + bN1));
            float h0 = n0 + z0 * (hold[rp][0] - n0);
            float h1 = n1 + z1 * (hold[rp][1] - n1);
            hold[rp][0] = h0; hold[rp][1] = h1;

            __nv_bfloat16 h0h = __float2bfloat16(h0);
            __nv_bfloat16 h1h = __float2bfloat16(h1);
            float l0 = h0 - __bfloat162float(h0h);
            float l1 = h1 - __bfloat162float(h1h);
            *reinterpret_cast<uint32_t*>(&Hhi[row * WPAD + j0]) =
                pack_bf16x2(h0h, h1h);
            *reinterpret_cast<uint32_t*>(&Hlo[row * WPAD + j0]) =
                cvt_bf16x2(l0, l1);

            float2 o; o.x = h0; o.y = h1;
            *reinterpret_cast<float2*>(
                &out[((size_t)(b0 + row) * TT + t) * HH + j0]) = o;
        }
        __syncthreads();   // new h visible before next step's ldmatrix
    }

    if (write_hT) {
        float* outF = out + (size_t)BATCH * TT * HH;
#pragma unroll
        for (int rp = 0; rp < 2; ++rp) {
            int row = mt * 16 + g8 + rp * 8;
            float2 o; o.x = hold[rp][0]; o.y = hold[rp][1];
            *reinterpret_cast<float2*>(&outF[(size_t)(b0 + row) * HH + j0]) = o;
        }
    }
}

// =====================================================================
extern "C" void kernel_launch(void* const* d_in, const int* in_sizes, int n_in,
                              void* d_out, int out_size)
{
    const float* x   = (const float*)d_in[0];
    const float* Wih = (const float*)d_in[1];
    const float* Whh = (const float*)d_in[2];
    const float* bih = (const float*)d_in[3];
    const float* bhh = (const float*)d_in[4];
    float* out = (float*)d_out;
    (void)in_sizes; (void)n_in;

    cudaFuncSetAttribute(xproj_mma_kernel,
                         cudaFuncAttributeMaxDynamicSharedMemorySize, XP2_SMEM_BYTES);
    cudaFuncSetAttribute(gru_mma_kernel,
                         cudaFuncAttributeMaxDynamicSharedMemorySize, R_SMEM_BYTES);

    int write_hT = (out_size >= BATCH * TT * HH + BATCH * HH) ? 1 : 0;

    xproj_mma_kernel<<<148, 512, XP2_SMEM_BYTES>>>(x, Wih, bih);
    gru_mma_kernel<<<BATCH / 32, 1024, R_SMEM_BYTES>>>(Whh, bhh, out, write_hT);
}

// round 11
// speedup vs baseline: 1.0619x; 1.0619x over previous
#include <cuda_runtime.h>
#include <cuda_bf16.h>
#include <cstdint>

// Problem constants
#define BATCH 4096
#define TT    120
#define II    64
#define HH    128
#define G3    384   // 3*H

// 755MB fp32 scratch for precomputed input gates, layout [T][B][3H]
__device__ float g_xg[(size_t)TT * BATCH * G3];

__device__ __forceinline__ float sigf(float v) {
    return __fdividef(1.0f, 1.0f + __expf(-v));
}
__device__ __forceinline__ float tanhf_fast(float v) {
    return __fdividef(2.0f, 1.0f + __expf(-2.0f * v)) - 1.0f;
}

// ---------------- tensor-core helpers ----------------
__device__ __forceinline__ uint32_t s2u(const void* p) {
    return (uint32_t)__cvta_generic_to_shared(p);
}
__device__ __forceinline__ void ldsm_x4(uint32_t a[4], uint32_t addr) {
    asm volatile("ldmatrix.sync.aligned.m8n8.x4.shared.b16 {%0,%1,%2,%3}, [%4];"
                 : "=r"(a[0]), "=r"(a[1]), "=r"(a[2]), "=r"(a[3]) : "r"(addr));
}
// B operand: W stored [n][k] row-major == col-major B(k x n): load WITHOUT trans
__device__ __forceinline__ void ldsm_x2(uint32_t b[2], uint32_t addr) {
    asm volatile("ldmatrix.sync.aligned.m8n8.x2.shared.b16 {%0,%1}, [%2];"
                 : "=r"(b[0]), "=r"(b[1]) : "r"(addr));
}
__device__ __forceinline__ void mma16816(float c[4], const uint32_t a[4],
                                         const uint32_t b[2]) {
    asm volatile(
        "mma.sync.aligned.m16n8k16.row.col.f32.bf16.bf16.f32 "
        "{%0,%1,%2,%3}, {%4,%5,%6,%7}, {%8,%9}, {%0,%1,%2,%3};"
        : "+f"(c[0]), "+f"(c[1]), "+f"(c[2]), "+f"(c[3])
        : "r"(a[0]), "r"(a[1]), "r"(a[2]), "r"(a[3]), "r"(b[0]), "r"(b[1]));
}
// pack (lo_elem, hi_elem) floats -> bf16x2 with rounding (lo_elem in low half)
__device__ __forceinline__ uint32_t cvt_bf16x2(float lo_elem, float hi_elem) {
    uint32_t d;
    asm("cvt.rn.bf16x2.f32 %0, %1, %2;" : "=r"(d) : "f"(hi_elem), "f"(lo_elem));
    return d;
}
// pack two already-converted bf16 (a -> low half)
__device__ __forceinline__ uint32_t pack_bf16x2(__nv_bfloat16 a, __nv_bfloat16 b) {
    uint32_t d;
    asm("mov.b32 %0, {%1, %2};" : "=r"(d)
        : "h"(*(const unsigned short*)&a), "h"(*(const unsigned short*)&b));
    return d;
}
__device__ __forceinline__ void barx(int id, int cnt) {
    asm volatile("bar.sync %0, %1;" :: "r"(id), "r"(cnt) : "memory");
}

// =====================================================================
// Kernel 1: x_gates via tensor cores (bf16 hi/lo 3-pass mma).
// (unchanged — ~262us, near DRAM floor)
// =====================================================================
#define XW   72                  // padded k-row length (144B stride)
#define NT2  (TT * (BATCH / 64)) // 7680 tiles
#define XP2_SMEM_BYTES ((G3 * XW * 2 + 64 * XW * 2) * 2)   // 129024

__global__ void __launch_bounds__(512, 1)
xproj_mma_kernel(const float* __restrict__ x,
                 const float* __restrict__ Wih,
                 const float* __restrict__ bih)
{
    extern __shared__ __align__(16) char smemc[];
    __nv_bfloat16* Whi = reinterpret_cast<__nv_bfloat16*>(smemc);
    __nv_bfloat16* Wlo = Whi + G3 * XW;
    __nv_bfloat16* Xhi = Wlo + G3 * XW;
    __nv_bfloat16* Xlo = Xhi + 64 * XW;

    const int tid   = threadIdx.x;
    const int w     = tid >> 5;
    const int lane  = tid & 31;
    const int g8    = lane >> 2;
    const int cc    = lane & 3;
    const int jbase = w * 8;
    const int j0    = jbase + 2 * cc;

    for (int i = tid; i < G3 * II; i += 512) {
        int n = i >> 6, k = i & 63;
        float v = Wih[i];
        __nv_bfloat16 hi = __float2bfloat16(v);
        Whi[n * XW + k] = hi;
        Wlo[n * XW + k] = __float2bfloat16(v - __bfloat162float(hi));
    }

    const float bR0 = bih[j0],       bR1 = bih[j0 + 1];
    const float bZ0 = bih[128 + j0], bZ1 = bih[128 + j0 + 1];
    const float bN0 = bih[256 + j0], bN1 = bih[256 + j0 + 1];

    const int arow = lane & 15;
    const int acol = (lane >> 4) * 8;
    uint32_t aHi[4], aLo[4];
#pragma unroll
    for (int mt = 0; mt < 4; ++mt) {
        aHi[mt] = s2u(Xhi + (mt * 16 + arow) * XW + acol);
        aLo[mt] = s2u(Xlo + (mt * 16 + arow) * XW + acol);
    }
    const int l16  = lane & 15;
    const int brow = l16 & 7;
    const int bkh  = (l16 >> 3) & 1;
    uint32_t bHi[3], bLo[3];
#pragma unroll
    for (int g = 0; g < 3; ++g) {
        int nb = g * 128 + jbase;
        bHi[g] = s2u(Whi + (nb + brow) * XW + 8 * bkh);
        bLo[g] = s2u(Wlo + (nb + brow) * XW + 8 * bkh);
    }

    const int xrow = tid >> 3;
    const int xcol = (tid & 7) * 8;
    float4 pa, pb;

    int tile = blockIdx.x;
    if (tile < NT2) {
        int t = tile % TT, b0 = (tile / TT) << 6;
        const float4* p = reinterpret_cast<const float4*>(
            x + ((size_t)(b0 + xrow) * TT + t) * II + xcol);
        pa = p[0]; pb = p[1];
    }

    for (; tile < NT2; tile += 148) {
        const int t  = tile % TT;
        const int b0 = (tile / TT) << 6;

        __syncthreads();

        {
            float v[8] = {pa.x, pa.y, pa.z, pa.w, pb.x, pb.y, pb.z, pb.w};
            __nv_bfloat16* hp = Xhi + xrow * XW + xcol;
            __nv_bfloat16* lp = Xlo + xrow * XW + xcol;
#pragma unroll
            for (int e = 0; e < 4; ++e) {
                float a0 = v[2 * e], a1 = v[2 * e + 1];
                __nv_bfloat16 h0 = __float2bfloat16(a0);
                __nv_bfloat16 h1 = __float2bfloat16(a1);
                *reinterpret_cast<uint32_t*>(hp + 2 * e) = pack_bf16x2(h0, h1);
                *reinterpret_cast<uint32_t*>(lp + 2 * e) =
                    cvt_bf16x2(a0 - __bfloat162float(h0), a1 - __bfloat162float(h1));
            }
        }

        {
            int nxt = tile + 148;
            if (nxt < NT2) {
                int tn = nxt % TT, bn = (nxt / TT) << 6;
                const float4* p = reinterpret_cast<const float4*>(
                    x + ((size_t)(bn + xrow) * TT + tn) * II + xcol);
                pa = p[0]; pb = p[1];
            }
        }

        __syncthreads();

        float C[4][3][4];
#pragma unroll
        for (int mt = 0; mt < 4; ++mt)
#pragma unroll
            for (int g = 0; g < 3; ++g)
#pragma unroll
                for (int e = 0; e < 4; ++e) C[mt][g][e] = 0.0f;

#pragma unroll
        for (int c8 = 0; c8 < 4; ++c8) {
            const uint32_t off = c8 * 32;
            uint32_t ahi[4][4], alo[4][4];
#pragma unroll
            for (int mt = 0; mt < 4; ++mt) {
                ldsm_x4(ahi[mt], aHi[mt] + off);
                ldsm_x4(alo[mt], aLo[mt] + off);
            }
#pragma unroll
            for (int g = 0; g < 3; ++g) {
                uint32_t bh[2], bl_[2];
                ldsm_x2(bh,  bHi[g] + off);
                ldsm_x2(bl_, bLo[g] + off);
#pragma unroll
                for (int mt = 0; mt < 4; ++mt) {
                    mma16816(C[mt][g], ahi[mt], bh);
                    mma16816(C[mt][g], alo[mt], bh);
                    mma16816(C[mt][g], ahi[mt], bl_);
                }
            }
        }

#pragma unroll
        for (int mt = 0; mt < 4; ++mt) {
#pragma unroll
            for (int rp = 0; rp < 2; ++rp) {
                int row = mt * 16 + g8 + rp * 8;
                float* dst = g_xg + ((size_t)t * BATCH + b0 + row) * G3 + j0;
                float2 o;
                o.x = C[mt][0][rp * 2] + bR0; o.y = C[mt][0][rp * 2 + 1] + bR1;
                *reinterpret_cast<float2*>(dst) = o;
                o.x = C[mt][1][rp * 2] + bZ0; o.y = C[mt][1][rp * 2 + 1] + bZ1;
                *reinterpret_cast<float2*>(dst + 128) = o;
                o.x = C[mt][2][rp * 2] + bN0; o.y = C[mt][2][rp * 2 + 1] + bN1;
                *reinterpret_cast<float2*>(dst + 256) = o;
            }
        }
    }
}

// =====================================================================
// Kernel 2: GRU recurrence, 512 thr, split into TWO INDEPENDENT 256-thr
// halves (rows 0-15 / 16-31 are independent recurrences). Named
// barriers (id 1+half, 256) -> halves slip; tensor phase of one half
// overlaps MUFU/store epilogue of the other.
// Warp layout per half: 8 warps, warp wl owns j-cols [16wl,16wl+16)
// across all 3 gates (6 n-tiles). One ldsm_x4 per gate per plane
// fetches both n-tiles (lane-group addressing).
// SMEM: Whi/Wlo [384][136] bf16, Hhi/Hlo [32][136] bf16. 226.3 KB.
// =====================================================================
#define WPAD  136
#define R_SMEM_BYTES ((384 * WPAD * 2 + 32 * WPAD * 2) * 2)   // 226304

__global__ void __launch_bounds__(512, 1)
gru_mma_kernel(const float* __restrict__ Whh,
               const float* __restrict__ bhh,
               float* __restrict__ out,
               int write_hT)
{
    extern __shared__ __align__(16) char smemc[];
    __nv_bfloat16* Whi = reinterpret_cast<__nv_bfloat16*>(smemc);
    __nv_bfloat16* Wlo = Whi + 384 * WPAD;
    __nv_bfloat16* Hhi = Wlo + 384 * WPAD;
    __nv_bfloat16* Hlo = Hhi + 32 * WPAD;

    const int tid   = threadIdx.x;
    const int w     = tid >> 5;          // 0..15
    const int lane  = tid & 31;
    const int half  = w >> 3;            // 0..1 : independent row group
    const int wl    = w & 7;             // warp within half
    const int jbase = wl * 16;           // 16 j-cols per warp
    const int g8    = lane >> 2;
    const int cc    = lane & 3;
    const int j0    = jbase + 2 * cc;
    const int b0    = blockIdx.x * 32;
    const int barid = 1 + half;

    for (int i = tid; i < G3 * HH; i += 512) {
        int n = i >> 7, k = i & 127;
        float v = Whh[i];
        __nv_bfloat16 hi = __float2bfloat16(v);
        Whi[n * WPAD + k] = hi;
        Wlo[n * WPAD + k] = __float2bfloat16(v - __bfloat162float(hi));
    }
    for (int i = tid; i < 32 * WPAD; i += 512) {
        Hhi[i] = __float2bfloat16(0.0f);
        Hlo[i] = __float2bfloat16(0.0f);
    }

    // biases for this thread's 4 j-cols (j0, j0+1, j0+8, j0+9) x 3 gates
    float bR[4], bZ[4], bN[4];
#pragma unroll
    for (int s = 0; s < 2; ++s) {
        bR[2*s]   = bhh[j0 + 8*s];       bR[2*s+1] = bhh[j0 + 8*s + 1];
        bZ[2*s]   = bhh[128 + j0 + 8*s]; bZ[2*s+1] = bhh[128 + j0 + 8*s + 1];
        bN[2*s]   = bhh[256 + j0 + 8*s]; bN[2*s+1] = bhh[256 + j0 + 8*s + 1];
    }

    __syncthreads();

    // A (h): x4 over this half's 16 rows
    const int arow = lane & 15;
    const int acol = (lane >> 4) * 8;
    const uint32_t aHi = s2u(Hhi + (half * 16 + arow) * WPAD + acol);
    const uint32_t aLo = s2u(Hlo + (half * 16 + arow) * WPAD + acol);

    // B: per gate one x4 covering both n-tiles:
    // lanes 0-7: tile0 k0-7 | 8-15: tile0 k8-15 | 16-23: tile1 k0-7 | 24-31: tile1 k8-15
    const int brow = (lane & 7) + ((lane >> 4) << 3);   // row within 16-col group
    const int bkh  = (lane >> 3) & 1;
    uint32_t bHiA[3], bLoA[3];
#pragma unroll
    for (int g = 0; g < 3; ++g) {
        int nb = g * 128 + jbase;
        bHiA[g] = s2u(Whi + (nb + brow) * WPAD + 8 * bkh);
        bLoA[g] = s2u(Wlo + (nb + brow) * WPAD + 8 * bkh);
    }

    // hold[rp (row g8 / g8+8)][4 cols: j0,j0+1,j0+8,j0+9]
    float hold[2][4];
#pragma unroll
    for (int rp = 0; rp < 2; ++rp)
#pragma unroll
        for (int e = 0; e < 4; ++e) hold[rp][e] = 0.0f;

    const int R0 = half * 16 + g8;   // first local batch row

    for (int t = 0; t < TT; ++t) {
        // ---- prefetch input gates for this thread's 2 rows x 4 cols ----
        float2 xr[2][2], xz[2][2], xn[2][2];
#pragma unroll
        for (int rp = 0; rp < 2; ++rp) {
            const float* rowp =
                g_xg + ((size_t)t * BATCH + b0 + R0 + rp * 8) * G3 + j0;
#pragma unroll
            for (int s = 0; s < 2; ++s) {
                xr[rp][s] = *reinterpret_cast<const float2*>(rowp + 8 * s);
                xz[rp][s] = *reinterpret_cast<const float2*>(rowp + 128 + 8 * s);
                xn[rp][s] = *reinterpret_cast<const float2*>(rowp + 256 + 8 * s);
            }
        }

        // ---- mma: C[gate][tile][4] ----
        float C[3][2][4];
#pragma unroll
        for (int g = 0; g < 3; ++g)
#pragma unroll
            for (int s = 0; s < 2; ++s)
#pragma unroll
                for (int e = 0; e < 4; ++e) C[g][s][e] = 0.0f;

#pragma unroll
        for (int c8 = 0; c8 < 8; ++c8) {
            const uint32_t off = c8 * 32;
            uint32_t ah[4], al[4];
            ldsm_x4(ah, aHi + off);
            ldsm_x4(al, aLo + off);
            uint32_t bh[3][4], bl[3][4];
#pragma unroll
            for (int g = 0; g < 3; ++g) {
                ldsm_x4(bh[g], bHiA[g] + off);
                ldsm_x4(bl[g], bLoA[g] + off);
            }
#pragma unroll
            for (int g = 0; g < 3; ++g) {
#pragma unroll
                for (int s = 0; s < 2; ++s) {
                    mma16816(C[g][s], ah, bh[g] + 2 * s);
                    mma16816(C[g][s], al, bh[g] + 2 * s);
                    mma16816(C[g][s], ah, bl[g] + 2 * s);
                }
            }
        }

        barx(barid, 256);   // this half's ldmatrix reads of h done

        // ---- gates + h update + stores ----
#pragma unroll
        for (int rp = 0; rp < 2; ++rp) {
            const int row = R0 + rp * 8;
            float hv[4];
#pragma unroll
            for (int s = 0; s < 2; ++s) {
                float hr0 = C[0][s][rp * 2], hr1 = C[0][s][rp * 2 + 1];
                float hz0 = C[1][s][rp * 2], hz1 = C[1][s][rp * 2 + 1];
                float hn0 = C[2][s][rp * 2], hn1 = C[2][s][rp * 2 + 1];

                float r0 = sigf(xr[rp][s].x + hr0 + bR[2*s]);
                float r1 = sigf(xr[rp][s].y + hr1 + bR[2*s+1]);
                float z0 = sigf(xz[rp][s].x + hz0 + bZ[2*s]);
                float z1 = sigf(xz[rp][s].y + hz1 + bZ[2*s+1]);
                float n0 = tanhf_fast(xn[rp][s].x + r0 * (hn0 + bN[2*s]));
                float n1 = tanhf_fast(xn[rp][s].y + r1 * (hn1 + bN[2*s+1]));
                float h0 = n0 + z0 * (hold[rp][2*s]   - n0);
                float h1 = n1 + z1 * (hold[rp][2*s+1] - n1);
                hold[rp][2*s]   = h0;
                hold[rp][2*s+1] = h1;
                hv[2*s] = h0; hv[2*s+1] = h1;

                __nv_bfloat16 h0h = __float2bfloat16(h0);
                __nv_bfloat16 h1h = __float2bfloat16(h1);
                *reinterpret_cast<uint32_t*>(&Hhi[row * WPAD + j0 + 8*s]) =
                    pack_bf16x2(h0h, h1h);
                *reinterpret_cast<uint32_t*>(&Hlo[row * WPAD + j0 + 8*s]) =
                    cvt_bf16x2(h0 - __bfloat162float(h0h),
                               h1 - __bfloat162float(h1h));
            }
            float* op = &out[((size_t)(b0 + row) * TT + t) * HH + j0];
            *reinterpret_cast<float2*>(op)     = make_float2(hv[0], hv[1]);
            *reinterpret_cast<float2*>(op + 8) = make_float2(hv[2], hv[3]);
        }

        barx(barid, 256);   // new h visible before next step's ldmatrix
    }

    if (write_hT) {
        float* outF = out + (size_t)BATCH * TT * HH;
#pragma unroll
        for (int rp = 0; rp < 2; ++rp) {
            int row = R0 + rp * 8;
            float* op = &outF[(size_t)(b0 + row) * HH + j0];
            *reinterpret_cast<float2*>(op)     = make_float2(hold[rp][0], hold[rp][1]);
            *reinterpret_cast<float2*>(op + 8) = make_float2(hold[rp][2], hold[rp][3]);
        }
    }
}

// =====================================================================
extern "C" void kernel_launch(void* const* d_in, const int* in_sizes, int n_in,
                              void* d_out, int out_size)
{
    const float* x   = (const float*)d_in[0];
    const float* Wih = (const float*)d_in[1];
    const float* Whh = (const float*)d_in[2];
    const float* bih = (const float*)d_in[3];
    const float* bhh = (const float*)d_in[4];
    float* out = (float*)d_out;
    (void)in_sizes; (void)n_in;

    cudaFuncSetAttribute(xproj_mma_kernel,
                         cudaFuncAttributeMaxDynamicSharedMemorySize, XP2_SMEM_BYTES);
    cudaFuncSetAttribute(gru_mma_kernel,
                         cudaFuncAttributeMaxDynamicSharedMemorySize, R_SMEM_BYTES);

    int write_hT = (out_size >= BATCH * TT * HH + BATCH * HH) ? 1 : 0;

    xproj_mma_kernel<<<148, 512, XP2_SMEM_BYTES>>>(x, Wih, bih);
    gru_mma_kernel<<<BATCH / 32, 512, R_SMEM_BYTES>>>(Whh, bhh, out, write_hT);
}

// round 12
// speedup vs baseline: 1.0986x; 1.0345x over previous
#include <cuda_runtime.h>
#include <cuda_bf16.h>
#include <cstdint>

// Problem constants
#define BATCH 4096
#define TT    120
#define II    64
#define HH    128
#define G3    384   // 3*H

// 755MB fp32 scratch for precomputed input gates, layout [T][B][3H]
__device__ float g_xg[(size_t)TT * BATCH * G3];

__device__ __forceinline__ float sigf(float v) {
    return __fdividef(1.0f, 1.0f + __expf(-v));
}
__device__ __forceinline__ float tanhf_fast(float v) {
    return __fdividef(2.0f, 1.0f + __expf(-2.0f * v)) - 1.0f;
}

// ---------------- tensor-core helpers ----------------
__device__ __forceinline__ uint32_t s2u(const void* p) {
    return (uint32_t)__cvta_generic_to_shared(p);
}
__device__ __forceinline__ void ldsm_x4(uint32_t a[4], uint32_t addr) {
    asm volatile("ldmatrix.sync.aligned.m8n8.x4.shared.b16 {%0,%1,%2,%3}, [%4];"
                 : "=r"(a[0]), "=r"(a[1]), "=r"(a[2]), "=r"(a[3]) : "r"(addr));
}
// B operand: W stored [n][k] row-major == col-major B(k x n): load WITHOUT trans
__device__ __forceinline__ void ldsm_x2(uint32_t b[2], uint32_t addr) {
    asm volatile("ldmatrix.sync.aligned.m8n8.x2.shared.b16 {%0,%1}, [%2];"
                 : "=r"(b[0]), "=r"(b[1]) : "r"(addr));
}
__device__ __forceinline__ void mma16816(float c[4], const uint32_t a[4],
                                         const uint32_t b[2]) {
    asm volatile(
        "mma.sync.aligned.m16n8k16.row.col.f32.bf16.bf16.f32 "
        "{%0,%1,%2,%3}, {%4,%5,%6,%7}, {%8,%9}, {%0,%1,%2,%3};"
        : "+f"(c[0]), "+f"(c[1]), "+f"(c[2]), "+f"(c[3])
        : "r"(a[0]), "r"(a[1]), "r"(a[2]), "r"(a[3]), "r"(b[0]), "r"(b[1]));
}
// pack (lo_elem, hi_elem) floats -> bf16x2 with rounding (lo_elem in low half)
__device__ __forceinline__ uint32_t cvt_bf16x2(float lo_elem, float hi_elem) {
    uint32_t d;
    asm("cvt.rn.bf16x2.f32 %0, %1, %2;" : "=r"(d) : "f"(hi_elem), "f"(lo_elem));
    return d;
}
// pack two already-converted bf16 (a -> low half)
__device__ __forceinline__ uint32_t pack_bf16x2(__nv_bfloat16 a, __nv_bfloat16 b) {
    uint32_t d;
    asm("mov.b32 %0, {%1, %2};" : "=r"(d)
        : "h"(*(const unsigned short*)&a), "h"(*(const unsigned short*)&b));
    return d;
}
__device__ __forceinline__ void barx(int id, int cnt) {
    asm volatile("bar.sync %0, %1;" :: "r"(id), "r"(cnt) : "memory");
}

// =====================================================================
// Kernel 1: x_gates via tensor cores (bf16 hi/lo 3-pass mma).
// (unchanged — ~262us, near DRAM floor)
// =====================================================================
#define XW   72                  // padded k-row length (144B stride)
#define NT2  (TT * (BATCH / 64)) // 7680 tiles
#define XP2_SMEM_BYTES ((G3 * XW * 2 + 64 * XW * 2) * 2)   // 129024

__global__ void __launch_bounds__(512, 1)
xproj_mma_kernel(const float* __restrict__ x,
                 const float* __restrict__ Wih,
                 const float* __restrict__ bih)
{
    extern __shared__ __align__(16) char smemc[];
    __nv_bfloat16* Whi = reinterpret_cast<__nv_bfloat16*>(smemc);
    __nv_bfloat16* Wlo = Whi + G3 * XW;
    __nv_bfloat16* Xhi = Wlo + G3 * XW;
    __nv_bfloat16* Xlo = Xhi + 64 * XW;

    const int tid   = threadIdx.x;
    const int w     = tid >> 5;
    const int lane  = tid & 31;
    const int g8    = lane >> 2;
    const int cc    = lane & 3;
    const int jbase = w * 8;
    const int j0    = jbase + 2 * cc;

    for (int i = tid; i < G3 * II; i += 512) {
        int n = i >> 6, k = i & 63;
        float v = Wih[i];
        __nv_bfloat16 hi = __float2bfloat16(v);
        Whi[n * XW + k] = hi;
        Wlo[n * XW + k] = __float2bfloat16(v - __bfloat162float(hi));
    }

    const float bR0 = bih[j0],       bR1 = bih[j0 + 1];
    const float bZ0 = bih[128 + j0], bZ1 = bih[128 + j0 + 1];
    const float bN0 = bih[256 + j0], bN1 = bih[256 + j0 + 1];

    const int arow = lane & 15;
    const int acol = (lane >> 4) * 8;
    uint32_t aHi[4], aLo[4];
#pragma unroll
    for (int mt = 0; mt < 4; ++mt) {
        aHi[mt] = s2u(Xhi + (mt * 16 + arow) * XW + acol);
        aLo[mt] = s2u(Xlo + (mt * 16 + arow) * XW + acol);
    }
    const int l16  = lane & 15;
    const int brow = l16 & 7;
    const int bkh  = (l16 >> 3) & 1;
    uint32_t bHi[3], bLo[3];
#pragma unroll
    for (int g = 0; g < 3; ++g) {
        int nb = g * 128 + jbase;
        bHi[g] = s2u(Whi + (nb + brow) * XW + 8 * bkh);
        bLo[g] = s2u(Wlo + (nb + brow) * XW + 8 * bkh);
    }

    const int xrow = tid >> 3;
    const int xcol = (tid & 7) * 8;
    float4 pa, pb;

    int tile = blockIdx.x;
    if (tile < NT2) {
        int t = tile % TT, b0 = (tile / TT) << 6;
        const float4* p = reinterpret_cast<const float4*>(
            x + ((size_t)(b0 + xrow) * TT + t) * II + xcol);
        pa = p[0]; pb = p[1];
    }

    for (; tile < NT2; tile += 148) {
        const int t  = tile % TT;
        const int b0 = (tile / TT) << 6;

        __syncthreads();

        {
            float v[8] = {pa.x, pa.y, pa.z, pa.w, pb.x, pb.y, pb.z, pb.w};
            __nv_bfloat16* hp = Xhi + xrow * XW + xcol;
            __nv_bfloat16* lp = Xlo + xrow * XW + xcol;
#pragma unroll
            for (int e = 0; e < 4; ++e) {
                float a0 = v[2 * e], a1 = v[2 * e + 1];
                __nv_bfloat16 h0 = __float2bfloat16(a0);
                __nv_bfloat16 h1 = __float2bfloat16(a1);
                *reinterpret_cast<uint32_t*>(hp + 2 * e) = pack_bf16x2(h0, h1);
                *reinterpret_cast<uint32_t*>(lp + 2 * e) =
                    cvt_bf16x2(a0 - __bfloat162float(h0), a1 - __bfloat162float(h1));
            }
        }

        {
            int nxt = tile + 148;
            if (nxt < NT2) {
                int tn = nxt % TT, bn = (nxt / TT) << 6;
                const float4* p = reinterpret_cast<const float4*>(
                    x + ((size_t)(bn + xrow) * TT + tn) * II + xcol);
                pa = p[0]; pb = p[1];
            }
        }

        __syncthreads();

        float C[4][3][4];
#pragma unroll
        for (int mt = 0; mt < 4; ++mt)
#pragma unroll
            for (int g = 0; g < 3; ++g)
#pragma unroll
                for (int e = 0; e < 4; ++e) C[mt][g][e] = 0.0f;

#pragma unroll
        for (int c8 = 0; c8 < 4; ++c8) {
            const uint32_t off = c8 * 32;
            uint32_t ahi[4][4], alo[4][4];
#pragma unroll
            for (int mt = 0; mt < 4; ++mt) {
                ldsm_x4(ahi[mt], aHi[mt] + off);
                ldsm_x4(alo[mt], aLo[mt] + off);
            }
#pragma unroll
            for (int g = 0; g < 3; ++g) {
                uint32_t bh[2], bl_[2];
                ldsm_x2(bh,  bHi[g] + off);
                ldsm_x2(bl_, bLo[g] + off);
#pragma unroll
                for (int mt = 0; mt < 4; ++mt) {
                    mma16816(C[mt][g], ahi[mt], bh);
                    mma16816(C[mt][g], alo[mt], bh);
                    mma16816(C[mt][g], ahi[mt], bl_);
                }
            }
        }

#pragma unroll
        for (int mt = 0; mt < 4; ++mt) {
#pragma unroll
            for (int rp = 0; rp < 2; ++rp) {
                int row = mt * 16 + g8 + rp * 8;
                float* dst = g_xg + ((size_t)t * BATCH + b0 + row) * G3 + j0;
                float2 o;
                o.x = C[mt][0][rp * 2] + bR0; o.y = C[mt][0][rp * 2 + 1] + bR1;
                *reinterpret_cast<float2*>(dst) = o;
                o.x = C[mt][1][rp * 2] + bZ0; o.y = C[mt][1][rp * 2 + 1] + bZ1;
                *reinterpret_cast<float2*>(dst + 128) = o;
                o.x = C[mt][2][rp * 2] + bN0; o.y = C[mt][2][rp * 2 + 1] + bN1;
                *reinterpret_cast<float2*>(dst + 256) = o;
            }
        }
    }
}

// =====================================================================
// Kernel 2: GRU recurrence, 512 thr, TWO INDEPENDENT 256-thr halves
// (rows 0-15 / 16-31) forced into ANTI-PHASE:
//   half A per step: { mma ; bar3(512) ; epilogue }
//   half B per step: { bar3(512) ; mma ; epilogue }
// Steady state: A.epi || B.mma, then A.mma(t+1) || B.epi(t) — the
// MUFU-bound epilogue of one half overlaps the tensor-bound mma of the
// other. Within-half read/write hazards use bar(1+half, 256).
// SMEM: Whi/Wlo [384][136] bf16, Hhi/Hlo [32][136] bf16. 226.3 KB.
// =====================================================================
#define WPAD  136
#define R_SMEM_BYTES ((384 * WPAD * 2 + 32 * WPAD * 2) * 2)   // 226304

__global__ void __launch_bounds__(512, 1)
gru_mma_kernel(const float* __restrict__ Whh,
               const float* __restrict__ bhh,
               float* __restrict__ out,
               int write_hT)
{
    extern __shared__ __align__(16) char smemc[];
    __nv_bfloat16* Whi = reinterpret_cast<__nv_bfloat16*>(smemc);
    __nv_bfloat16* Wlo = Whi + 384 * WPAD;
    __nv_bfloat16* Hhi = Wlo + 384 * WPAD;
    __nv_bfloat16* Hlo = Hhi + 32 * WPAD;

    const int tid   = threadIdx.x;
    const int w     = tid >> 5;          // 0..15
    const int lane  = tid & 31;
    const int half  = w >> 3;            // 0..1 : independent row group
    const int wl    = w & 7;             // warp within half
    const int jbase = wl * 16;           // 16 j-cols per warp
    const int g8    = lane >> 2;
    const int cc    = lane & 3;
    const int j0    = jbase + 2 * cc;
    const int b0    = blockIdx.x * 32;
    const int barid = 1 + half;

    for (int i = tid; i < G3 * HH; i += 512) {
        int n = i >> 7, k = i & 127;
        float v = Whh[i];
        __nv_bfloat16 hi = __float2bfloat16(v);
        Whi[n * WPAD + k] = hi;
        Wlo[n * WPAD + k] = __float2bfloat16(v - __bfloat162float(hi));
    }
    for (int i = tid; i < 32 * WPAD; i += 512) {
        Hhi[i] = __float2bfloat16(0.0f);
        Hlo[i] = __float2bfloat16(0.0f);
    }

    // biases for this thread's 4 j-cols (j0, j0+1, j0+8, j0+9) x 3 gates
    float bR[4], bZ[4], bN[4];
#pragma unroll
    for (int s = 0; s < 2; ++s) {
        bR[2*s]   = bhh[j0 + 8*s];       bR[2*s+1] = bhh[j0 + 8*s + 1];
        bZ[2*s]   = bhh[128 + j0 + 8*s]; bZ[2*s+1] = bhh[128 + j0 + 8*s + 1];
        bN[2*s]   = bhh[256 + j0 + 8*s]; bN[2*s+1] = bhh[256 + j0 + 8*s + 1];
    }

    __syncthreads();

    // A (h): x4 over this half's 16 rows
    const int arow = lane & 15;
    const int acol = (lane >> 4) * 8;
    const uint32_t aHi = s2u(Hhi + (half * 16 + arow) * WPAD + acol);
    const uint32_t aLo = s2u(Hlo + (half * 16 + arow) * WPAD + acol);

    // B: per gate one x4 covering both n-tiles:
    // lanes 0-7: tile0 k0-7 | 8-15: tile0 k8-15 | 16-23: tile1 k0-7 | 24-31: tile1 k8-15
    const int brow = (lane & 7) + ((lane >> 4) << 3);
    const int bkh  = (lane >> 3) & 1;
    uint32_t bHiA[3], bLoA[3];
#pragma unroll
    for (int g = 0; g < 3; ++g) {
        int nb = g * 128 + jbase;
        bHiA[g] = s2u(Whi + (nb + brow) * WPAD + 8 * bkh);
        bLoA[g] = s2u(Wlo + (nb + brow) * WPAD + 8 * bkh);
    }

    float hold[2][4];
#pragma unroll
    for (int rp = 0; rp < 2; ++rp)
#pragma unroll
        for (int e = 0; e < 4; ++e) hold[rp][e] = 0.0f;

    const int R0 = half * 16 + g8;

    for (int t = 0; t < TT; ++t) {
        // ---- prefetch input gates (issued before any barrier wait) ----
        float2 xr[2][2], xz[2][2], xn[2][2];
#pragma unroll
        for (int rp = 0; rp < 2; ++rp) {
            const float* rowp =
                g_xg + ((size_t)t * BATCH + b0 + R0 + rp * 8) * G3 + j0;
#pragma unroll
            for (int s = 0; s < 2; ++s) {
                xr[rp][s] = *reinterpret_cast<const float2*>(rowp + 8 * s);
                xz[rp][s] = *reinterpret_cast<const float2*>(rowp + 128 + 8 * s);
                xn[rp][s] = *reinterpret_cast<const float2*>(rowp + 256 + 8 * s);
            }
        }

        // ---- anti-phase gate: half B waits for half A's mma to finish ----
        if (half == 1) barx(3, 512);

        // ---- mma: C[gate][tile][4] ----
        float C[3][2][4];
#pragma unroll
        for (int g = 0; g < 3; ++g)
#pragma unroll
            for (int s = 0; s < 2; ++s)
#pragma unroll
                for (int e = 0; e < 4; ++e) C[g][s][e] = 0.0f;

#pragma unroll
        for (int c8 = 0; c8 < 8; ++c8) {
            const uint32_t off = c8 * 32;
            uint32_t ah[4], al[4];
            ldsm_x4(ah, aHi + off);
            ldsm_x4(al, aLo + off);
            uint32_t bh[3][4], bl[3][4];
#pragma unroll
            for (int g = 0; g < 3; ++g) {
                ldsm_x4(bh[g], bHiA[g] + off);
                ldsm_x4(bl[g], bLoA[g] + off);
            }
#pragma unroll
            for (int g = 0; g < 3; ++g) {
#pragma unroll
                for (int s = 0; s < 2; ++s) {
                    mma16816(C[g][s], ah, bh[g] + 2 * s);
                    mma16816(C[g][s], al, bh[g] + 2 * s);
                    mma16816(C[g][s], ah, bl[g] + 2 * s);
                }
            }
        }

        // ---- anti-phase gate: half A signals its mma done ----
        if (half == 0) barx(3, 512);

        barx(barid, 256);   // this half's ldmatrix reads of h done

        // ---- gates + h update + stores ----
#pragma unroll
        for (int rp = 0; rp < 2; ++rp) {
            const int row = R0 + rp * 8;
            float hv[4];
#pragma unroll
            for (int s = 0; s < 2; ++s) {
                float hr0 = C[0][s][rp * 2], hr1 = C[0][s][rp * 2 + 1];
                float hz0 = C[1][s][rp * 2], hz1 = C[1][s][rp * 2 + 1];
                float hn0 = C[2][s][rp * 2], hn1 = C[2][s][rp * 2 + 1];

                float r0 = sigf(xr[rp][s].x + hr0 + bR[2*s]);
                float r1 = sigf(xr[rp][s].y + hr1 + bR[2*s+1]);
                float z0 = sigf(xz[rp][s].x + hz0 + bZ[2*s]);
                float z1 = sigf(xz[rp][s].y + hz1 + bZ[2*s+1]);
                float n0 = tanhf_fast(xn[rp][s].x + r0 * (hn0 + bN[2*s]));
                float n1 = tanhf_fast(xn[rp][s].y + r1 * (hn1 + bN[2*s+1]));
                float h0 = n0 + z0 * (hold[rp][2*s]   - n0);
                float h1 = n1 + z1 * (hold[rp][2*s+1] - n1);
                hold[rp][2*s]   = h0;
                hold[rp][2*s+1] = h1;
                hv[2*s] = h0; hv[2*s+1] = h1;

                __nv_bfloat16 h0h = __float2bfloat16(h0);
                __nv_bfloat16 h1h = __float2bfloat16(h1);
                *reinterpret_cast<uint32_t*>(&Hhi[row * WPAD + j0 + 8*s]) =
                    pack_bf16x2(h0h, h1h);
                *reinterpret_cast<uint32_t*>(&Hlo[row * WPAD + j0 + 8*s]) =
                    cvt_bf16x2(h0 - __bfloat162float(h0h),
                               h1 - __bfloat162float(h1h));
            }
            float* op = &out[((size_t)(b0 + row) * TT + t) * HH + j0];
            *reinterpret_cast<float2*>(op)     = make_float2(hv[0], hv[1]);
            *reinterpret_cast<float2*>(op + 8) = make_float2(hv[2], hv[3]);
        }

        barx(barid, 256);   // new h visible before next step's ldmatrix
    }

    if (write_hT) {
        float* outF = out + (size_t)BATCH * TT * HH;
#pragma unroll
        for (int rp = 0; rp < 2; ++rp) {
            int row = R0 + rp * 8;
            float* op = &outF[(size_t)(b0 + row) * HH + j0];
            *reinterpret_cast<float2*>(op)     = make_float2(hold[rp][0], hold[rp][1]);
            *reinterpret_cast<float2*>(op + 8) = make_float2(hold[rp][2], hold[rp][3]);
        }
    }
}

// =====================================================================
extern "C" void kernel_launch(void* const* d_in, const int* in_sizes, int n_in,
                              void* d_out, int out_size)
{
    const float* x   = (const float*)d_in[0];
    const float* Wih = (const float*)d_in[1];
    const float* Whh = (const float*)d_in[2];
    const float* bih = (const float*)d_in[3];
    const float* bhh = (const float*)d_in[4];
    float* out = (float*)d_out;
    (void)in_sizes; (void)n_in;

    cudaFuncSetAttribute(xproj_mma_kernel,
                         cudaFuncAttributeMaxDynamicSharedMemorySize, XP2_SMEM_BYTES);
    cudaFuncSetAttribute(gru_mma_kernel,
                         cudaFuncAttributeMaxDynamicSharedMemorySize, R_SMEM_BYTES);

    int write_hT = (out_size >= BATCH * TT * HH + BATCH * HH) ? 1 : 0;

    xproj_mma_kernel<<<148, 512, XP2_SMEM_BYTES>>>(x, Wih, bih);
    gru_mma_kernel<<<BATCH / 32, 512, R_SMEM_BYTES>>>(Whh, bhh, out, write_hT);
}